// round 5
// baseline (speedup 1.0000x reference)
#include <cuda_runtime.h>
#include <cstddef>

#define BB   16
#define SS   4096
#define DIN  512
#define DM   1024
#define NH   16
#define HD   64

// ---------------- scratch (no allocations allowed) ----------------
__device__ float g_x1e[BB * DM];
__device__ float g_q[BB * DM];
__device__ float g_t[BB * NH * DM];             // 1 MB
__device__ float g_uT[BB * DIN * NH];           // 0.5 MB, [b][i][h]
__device__ float g_scores[BB * NH * SS];        // 4 MB (unnormalized exp weights)
__device__ float g_ypart[32 * BB * NH * DIN];   // 16.8 MB, [c][b][h][d]
__device__ float g_wsump[32 * BB * NH];         // per-chunk sum of exp
__device__ float g_y[BB * NH * DIN];
__device__ float g_av[BB * DM];
__device__ float g_part[2097152];               // 8 MB split-K partials

typedef unsigned long long ull;

// ---------------- f32x2 packed-FMA helpers ----------------
__device__ __forceinline__ ull pk2(float lo, float hi) {
    ull r;
    asm("mov.b64 %0, {%1, %2};" : "=l"(r) : "f"(lo), "f"(hi));
    return r;
}
__device__ __forceinline__ ull ff2(ull a, ull b, ull c) {
    ull d;
    asm("fma.rn.f32x2 %0, %1, %2, %3;" : "=l"(d) : "l"(a), "l"(b), "l"(c));
    return d;
}
__device__ __forceinline__ void up2(float& lo, float& hi, ull a) {
    asm("mov.b64 {%0, %1}, %2;" : "=f"(lo), "=f"(hi) : "l"(a));
}

// ---------------- fused 16-row dense: out[16][1024] = X[16][K] @ W[K][1024] + bias
template <int K>
__global__ void k_dense16(const float* __restrict__ X, const float* __restrict__ W,
                          const float* __restrict__ bias, float* __restrict__ out) {
    __shared__ float xs[256][17];
    __shared__ float ps[16][256];
    int tid = threadIdx.x;
    int jl = tid & 15, ks = tid >> 4;
    int j = blockIdx.x * 16 + jl;
    float acc[BB];
#pragma unroll
    for (int b = 0; b < BB; ++b) acc[b] = 0.f;

    for (int k0 = 0; k0 < K; k0 += 256) {
        __syncthreads();
#pragma unroll
        for (int i = 0; i < 16; ++i) {
            int l = tid + i * 256;
            int k = l & 255, b = l >> 8;
            xs[k][b] = X[b * K + k0 + k];
        }
        __syncthreads();
#pragma unroll 8
        for (int kk = ks * 16; kk < ks * 16 + 16; ++kk) {
            float w = W[(size_t)(k0 + kk) * DM + j];
#pragma unroll
            for (int b = 0; b < BB; ++b) acc[b] += w * xs[kk][b];
        }
    }
#pragma unroll
    for (int b = 0; b < BB; ++b) ps[ks][b * 16 + jl] = acc[b];
    __syncthreads();
    {
        int b = tid >> 4, jj = tid & 15;
        float s = 0.f;
#pragma unroll
        for (int z = 0; z < 16; ++z) s += ps[z][tid];
        out[b * DM + blockIdx.x * 16 + jj] = s + bias[blockIdx.x * 16 + jj];
    }
}

// ---------------- t[b,h,j] = sum_d Wk[j, h*64+d] * q[b, h*64+d]
__global__ void k_t(const float* __restrict__ Wk) {
    int h = blockIdx.x, j0 = blockIdx.y * 128;
    int tid = threadIdx.x;
    int jl = tid & 31, bg = tid >> 5;
    __shared__ float qs[BB][HD];
    __shared__ float wk[32][65];
    for (int l = tid; l < BB * HD; l += 128) {
        int b = l >> 6, d = l & 63;
        qs[b][d] = g_q[b * DM + h * HD + d];
    }
    for (int st = 0; st < 4; ++st) {
        __syncthreads();
#pragma unroll
        for (int i = 0; i < 16; ++i) {
            int l = tid + i * 128;
            int r = l >> 6, d = l & 63;
            wk[r][d] = Wk[(size_t)(j0 + st * 32 + r) * DM + h * HD + d];
        }
        __syncthreads();
        float acc[4] = {0.f, 0.f, 0.f, 0.f};
#pragma unroll 8
        for (int d = 0; d < HD; ++d) {
            float w = wk[jl][d];
#pragma unroll
            for (int bb = 0; bb < 4; ++bb) acc[bb] += w * qs[bg * 4 + bb][d];
        }
        int j = j0 + st * 32 + jl;
#pragma unroll
        for (int bb = 0; bb < 4; ++bb)
            g_t[(size_t)((bg * 4 + bb) * NH + h) * DM + j] = acc[bb];
    }
}

// ---------------- double-buffered split-K GEMM with f32x2 (m-pairs)
// C[M,N] = A[M,K] @ B ; B is [N,K] (kmajor) or [K,N]
template <int MM, int NN, int KK, int SPLITS, bool BKMAJOR>
__global__ void k_gemm(const float* __restrict__ A, const float* __restrict__ Bm,
                       float* __restrict__ part) {
    constexpr int KC = KK / SPLITS, NS = KC / 16;
    __shared__ float Asm[2][16][64];
    __shared__ float Bsm[2][16][64];
    int n0 = blockIdx.x * 64, m0 = blockIdx.y * 64, k0 = blockIdx.z * KC;
    int tid = threadIdx.x;
    int tx = tid & 15, ty = tid >> 4;
    int am = tid >> 2, akq = tid & 3;     // staging coords (transposed scatter)
    int bkk = tid >> 4, bn4 = tid & 15;   // staging coords (row-major copy)
    float4 a4, b4;

#define GEMM_LD(kt)                                                                       \
    {                                                                                     \
        a4 = *(const float4*)(A + (size_t)(m0 + am) * KK + k0 + (kt) * 16 + akq * 4);     \
        if (BKMAJOR)                                                                      \
            b4 = *(const float4*)(Bm + (size_t)(n0 + am) * KK + k0 + (kt) * 16 + akq * 4);\
        else                                                                              \
            b4 = *(const float4*)(Bm + (size_t)(k0 + (kt) * 16 + bkk) * NN + n0 + bn4 * 4);\
    }
#define GEMM_ST(bf)                                                                       \
    {                                                                                     \
        Asm[bf][akq * 4 + 0][am] = a4.x; Asm[bf][akq * 4 + 1][am] = a4.y;                 \
        Asm[bf][akq * 4 + 2][am] = a4.z; Asm[bf][akq * 4 + 3][am] = a4.w;                 \
        if (BKMAJOR) {                                                                    \
            Bsm[bf][akq * 4 + 0][am] = b4.x; Bsm[bf][akq * 4 + 1][am] = b4.y;             \
            Bsm[bf][akq * 4 + 2][am] = b4.z; Bsm[bf][akq * 4 + 3][am] = b4.w;             \
        } else {                                                                          \
            *(float4*)&Bsm[bf][bkk][bn4 * 4] = b4;                                        \
        }                                                                                 \
    }

    GEMM_LD(0); GEMM_ST(0);
    ull acc[2][4] = {};
    for (int ks = 0; ks < NS; ++ks) {
        __syncthreads();
        int cur = ks & 1;
        if (ks + 1 < NS) GEMM_LD(ks + 1);
#pragma unroll
        for (int kk = 0; kk < 16; ++kk) {
            ulonglong2 ap = *(const ulonglong2*)&Asm[cur][kk][ty * 4];
            float4 bq = *(const float4*)&Bsm[cur][kk][tx * 4];
            ull bd;
            bd = pk2(bq.x, bq.x); acc[0][0] = ff2(ap.x, bd, acc[0][0]); acc[1][0] = ff2(ap.y, bd, acc[1][0]);
            bd = pk2(bq.y, bq.y); acc[0][1] = ff2(ap.x, bd, acc[0][1]); acc[1][1] = ff2(ap.y, bd, acc[1][1]);
            bd = pk2(bq.z, bq.z); acc[0][2] = ff2(ap.x, bd, acc[0][2]); acc[1][2] = ff2(ap.y, bd, acc[1][2]);
            bd = pk2(bq.w, bq.w); acc[0][3] = ff2(ap.x, bd, acc[0][3]); acc[1][3] = ff2(ap.y, bd, acc[1][3]);
        }
        if (ks + 1 < NS) GEMM_ST((ks + 1) & 1);
    }
#undef GEMM_LD
#undef GEMM_ST
    float lo[2][4], hi[2][4];
#pragma unroll
    for (int p = 0; p < 2; ++p)
#pragma unroll
        for (int n = 0; n < 4; ++n) up2(lo[p][n], hi[p][n], acc[p][n]);
    float* p = part + (size_t)blockIdx.z * MM * NN;
    *(float4*)(p + (size_t)(m0 + ty * 4 + 0) * NN + n0 + tx * 4) = make_float4(lo[0][0], lo[0][1], lo[0][2], lo[0][3]);
    *(float4*)(p + (size_t)(m0 + ty * 4 + 1) * NN + n0 + tx * 4) = make_float4(hi[0][0], hi[0][1], hi[0][2], hi[0][3]);
    *(float4*)(p + (size_t)(m0 + ty * 4 + 2) * NN + n0 + tx * 4) = make_float4(lo[1][0], lo[1][1], lo[1][2], lo[1][3]);
    *(float4*)(p + (size_t)(m0 + ty * 4 + 3) * NN + n0 + tx * 4) = make_float4(hi[1][0], hi[1][1], hi[1][2], hi[1][3]);
}

// ---------------- reduce u partials (16 splits) and write transposed g_uT[b][i][h]
__global__ void k_reduce_ut(const float* __restrict__ part) {
    int e = blockIdx.x * 256 + threadIdx.x;  // 131072 total
    float s = 0.f;
#pragma unroll
    for (int z = 0; z < 16; ++z) s += part[(size_t)z * 131072 + e];
    int m = e >> 9, n = e & 511;
    int b = m >> 4, h = m & 15;
    g_uT[(size_t)(b * DIN + n) * NH + h] = s;
}

// ---------------- scores: g_scores[b,h,s] = exp((x2[b,s,:] . u[b,h,:]) / 8)
// grid (16 b, 16 chunks of 256 s), block 256, dynamic smem, double-buffered staging
__global__ void k_scores(const float* __restrict__ x2) {
    extern __shared__ float sm[];
    float* uT = sm;                 // [512][16]
    float* xs = sm + DIN * NH;      // [2][256][20]
    const int XR = 20;
    int b = blockIdx.x;
    int s0 = blockIdx.y * 256;
    int tid = threadIdx.x;
    for (int l = tid; l < DIN * NH; l += 256) uT[l] = g_uT[(size_t)b * DIN * NH + l];
    const float* x2b = x2 + ((size_t)b * SS + s0) * DIN;
    int rr = tid >> 2, jq = tid & 3;
    float4 r0, r1, r2, r3;
#define SC_LD(j0)                                                                   \
    {                                                                               \
        r0 = *(const float4*)(x2b + (size_t)rr * DIN + (j0) + jq * 4);              \
        r1 = *(const float4*)(x2b + (size_t)(rr + 64) * DIN + (j0) + jq * 4);       \
        r2 = *(const float4*)(x2b + (size_t)(rr + 128) * DIN + (j0) + jq * 4);      \
        r3 = *(const float4*)(x2b + (size_t)(rr + 192) * DIN + (j0) + jq * 4);      \
    }
#define SC_ST(bf)                                                                   \
    {                                                                               \
        float* xb = xs + (bf) * 256 * XR + jq * 4;                                  \
        *(float4*)(xb + rr * XR) = r0;                                              \
        *(float4*)(xb + (rr + 64) * XR) = r1;                                       \
        *(float4*)(xb + (rr + 128) * XR) = r2;                                      \
        *(float4*)(xb + (rr + 192) * XR) = r3;                                      \
    }
    SC_LD(0); SC_ST(0);
    ull acc[8];
#pragma unroll
    for (int p = 0; p < 8; ++p) acc[p] = 0ull;
    for (int js = 0; js < 32; ++js) {
        __syncthreads();
        int cur = js & 1;
        if (js + 1 < 32) SC_LD((js + 1) * 16);
        const float* xr = xs + cur * 256 * XR + tid * XR;
#pragma unroll
        for (int j4 = 0; j4 < 4; ++j4) {
            float4 xq = *(const float4*)(xr + j4 * 4);
#pragma unroll
            for (int jj = 0; jj < 4; ++jj) {
                float xv = (&xq.x)[jj];
                ull xd = pk2(xv, xv);
                const ulonglong2* up = (const ulonglong2*)&uT[(js * 16 + j4 * 4 + jj) * NH];
                ulonglong2 u01 = up[0], u23 = up[1], u45 = up[2], u67 = up[3];
                acc[0] = ff2(xd, u01.x, acc[0]);
                acc[1] = ff2(xd, u01.y, acc[1]);
                acc[2] = ff2(xd, u23.x, acc[2]);
                acc[3] = ff2(xd, u23.y, acc[3]);
                acc[4] = ff2(xd, u45.x, acc[4]);
                acc[5] = ff2(xd, u45.y, acc[5]);
                acc[6] = ff2(xd, u67.x, acc[6]);
                acc[7] = ff2(xd, u67.y, acc[7]);
            }
        }
        if (js + 1 < 32) SC_ST((js + 1) & 1);
    }
#undef SC_LD
#undef SC_ST
#pragma unroll
    for (int p = 0; p < 8; ++p) {
        float lo, hi;
        up2(lo, hi, acc[p]);
        g_scores[((size_t)(b * NH + 2 * p) << 12) + s0 + tid]     = __expf(lo * 0.125f);
        g_scores[((size_t)(b * NH + 2 * p + 1) << 12) + s0 + tid] = __expf(hi * 0.125f);
    }
}

// ---------------- weighted-sum partials + per-chunk sumexp
// grid (16 b, 32 s-chunks of 128), block 128 (4 d per thread)
__global__ void k_wsum(const float* __restrict__ x3) {
    int b = blockIdx.x, c = blockIdx.y;
    int s0 = c * 128;
    __shared__ float at[128][20];
    int tid = threadIdx.x;
    for (int l = tid; l < NH * 128; l += 128) {
        int h = l >> 7, s = l & 127;
        at[s][h] = g_scores[((size_t)(b * NH + h) << 12) + s0 + s];
    }
    __syncthreads();
    if (tid < NH) {  // per-chunk sumexp partial (fixed order, deterministic)
        float s = 0.f;
#pragma unroll 8
        for (int i = 0; i < 128; ++i) s += at[i][tid];
        g_wsump[(c * BB + b) * NH + tid] = s;
    }
    ull acc[8][4];
#pragma unroll
    for (int p = 0; p < 8; ++p)
#pragma unroll
        for (int d = 0; d < 4; ++d) acc[p][d] = 0ull;
    int d0 = tid * 4;
    const float* x3b = x3 + ((size_t)b * SS + s0) * DIN + d0;
#pragma unroll 4
    for (int s = 0; s < 128; ++s) {
        float4 xv = *(const float4*)(x3b + (size_t)s * DIN);
        ull xd[4];
        xd[0] = pk2(xv.x, xv.x); xd[1] = pk2(xv.y, xv.y);
        xd[2] = pk2(xv.z, xv.z); xd[3] = pk2(xv.w, xv.w);
        const ulonglong2* wp = (const ulonglong2*)&at[s][0];
        ulonglong2 wA = wp[0], wB = wp[1], wC = wp[2], wD = wp[3];
        ull w[8] = {wA.x, wA.y, wB.x, wB.y, wC.x, wC.y, wD.x, wD.y};
#pragma unroll
        for (int p = 0; p < 8; ++p) {
#pragma unroll
            for (int d = 0; d < 4; ++d) acc[p][d] = ff2(xd[d], w[p], acc[p][d]);
        }
    }
    float* yp = g_ypart + ((size_t)(c * BB + b) * NH) * DIN;
#pragma unroll
    for (int p = 0; p < 8; ++p) {
        float lo[4], hi[4];
#pragma unroll
        for (int d = 0; d < 4; ++d) up2(lo[d], hi[d], acc[p][d]);
        *(float4*)(yp + (2 * p) * DIN + d0)     = make_float4(lo[0], lo[1], lo[2], lo[3]);
        *(float4*)(yp + (2 * p + 1) * DIN + d0) = make_float4(hi[0], hi[1], hi[2], hi[3]);
    }
}

// ---------------- y = (sum over chunks ypart) / (sum over chunks sumexp)
__global__ void k_reduce_norm() {
    int e = blockIdx.x * 256 + threadIdx.x;  // 131072
    int bh = e >> 9;
    float s = 0.f, w = 0.f;
#pragma unroll
    for (int c = 0; c < 32; ++c) {
        s += g_ypart[(size_t)c * 131072 + e];
        w += g_wsump[c * 256 + bh];
    }
    g_y[e] = s / w;
}

// ---------------- av[b, h*64+d] = sum_j (Σ ye_parts + be2)[j] * Wv[j, h*64+d] + bv
__global__ void k_av(const float* __restrict__ part, const float* __restrict__ be2,
                     const float* __restrict__ Wv, const float* __restrict__ bv) {
    int b = blockIdx.x, h = blockIdx.y;
    int d = threadIdx.x & 63, jq = threadIdx.x >> 6;
    __shared__ float yes[DM];
    __shared__ float red[4][64];
    for (int l = threadIdx.x; l < DM; l += 256) {
        float s = be2[l];
#pragma unroll
        for (int z = 0; z < 8; ++z) s += part[(size_t)z * 262144 + (size_t)(b * NH + h) * DM + l];
        yes[l] = s;
    }
    __syncthreads();
    float acc = 0.f;
    const float* wp = Wv + h * HD + d;
#pragma unroll 8
    for (int j = jq * 256; j < jq * 256 + 256; ++j) acc += yes[j] * wp[(size_t)j * DM];
    red[jq][d] = acc;
    __syncthreads();
    if (jq == 0) {
        float s = red[0][d] + red[1][d] + red[2][d] + red[3][d] + bv[h * HD + d];
        g_av[b * DM + h * HD + d] = s;
    }
}

// ---------------- launch ----------------
extern "C" void kernel_launch(void* const* d_in, const int* in_sizes, int n_in,
                              void* d_out, int out_size) {
    const float* x1  = (const float*)d_in[0];
    const float* x2  = (const float*)d_in[1];
    const float* x3  = (const float*)d_in[2];
    const float* We1 = (const float*)d_in[3];
    const float* be1 = (const float*)d_in[4];
    const float* We2 = (const float*)d_in[5];
    const float* be2 = (const float*)d_in[6];
    const float* Wq  = (const float*)d_in[7];
    const float* bq  = (const float*)d_in[8];
    const float* Wk  = (const float*)d_in[9];
    // d_in[10] = bk: cancels in normalization, exactly dropped
    const float* Wv  = (const float*)d_in[11];
    const float* bv  = (const float*)d_in[12];
    const float* Wo  = (const float*)d_in[13];
    const float* bo  = (const float*)d_in[14];
    float* out = (float*)d_out;

    float *pg_part, *pg_x1e, *pg_q, *pg_t, *pg_y, *pg_av;
    cudaGetSymbolAddress((void**)&pg_part, g_part);
    cudaGetSymbolAddress((void**)&pg_x1e,  g_x1e);
    cudaGetSymbolAddress((void**)&pg_q,    g_q);
    cudaGetSymbolAddress((void**)&pg_t,    g_t);
    cudaGetSymbolAddress((void**)&pg_y,    g_y);
    cudaGetSymbolAddress((void**)&pg_av,   g_av);

    const int SC_SMEM = (DIN * NH + 2 * 256 * 20) * 4;  // 73728 B
    cudaFuncSetAttribute(k_scores, cudaFuncAttributeMaxDynamicSharedMemorySize, SC_SMEM);

    // 1) x1e = x1 @ We1 + be1
    k_dense16<512><<<64, 256>>>(x1, We1, be1, pg_x1e);
    // 2) q = x1e @ Wq + bq
    k_dense16<1024><<<64, 256>>>(pg_x1e, Wq, bq, pg_q);
    // 3) t[b,h,j] = Wk_h @ q_h
    k_t<<<dim3(NH, 8), 128>>>(Wk);
    // 4) u = t @ We2^T  -> transposed g_uT
    k_gemm<256, 512, 1024, 16, true><<<dim3(8, 4, 16), 256>>>(pg_t, We2, pg_part);
    k_reduce_ut<<<512, 256>>>(pg_part);
    // 5) unnormalized exp scores (softmax max-shift dropped; normalization deferred)
    k_scores<<<dim3(BB, 16), 256, SC_SMEM>>>(x2);
    // 6) weighted sums + sumexp partials, then normalize into g_y
    k_wsum<<<dim3(BB, 32), 128>>>(x3);
    k_reduce_norm<<<512, 256>>>();
    // 7) ye partials = y @ We2   (be2 + reduction folded into k_av)
    k_gemm<256, 1024, 512, 8, false><<<dim3(16, 4, 8), 256>>>(pg_y, We2, pg_part);
    // 8) av = per-head (Σ ye_parts + be2) @ Wv_h + bv
    k_av<<<dim3(BB, NH), 256>>>(pg_part, be2, Wv, bv);
    // 9) out = av @ Wo + bo
    k_dense16<1024><<<64, 256>>>(pg_av, Wo, bo, out);
}

// round 6
// speedup vs baseline: 1.3494x; 1.3494x over previous
#include <cuda_runtime.h>
#include <cstddef>

#define BB   16
#define SS   4096
#define DIN  512
#define DM   1024
#define NH   16
#define HD   64

// ---------------- scratch (no allocations allowed) ----------------
__device__ float g_x1e[BB * DM];
__device__ float g_q[BB * DM];
__device__ float g_t[BB * NH * DM];             // 1 MB
__device__ float g_uT[BB * DIN * NH];           // 0.5 MB, [b][i][h]
__device__ float g_scores[BB * NH * SS];        // 4 MB (unnormalized exp weights)
__device__ float g_ypart[32 * BB * NH * DIN];   // 16.8 MB, [c][b][h][d]
__device__ float g_wsump[32 * BB * NH];         // per-chunk sum of exp
__device__ float g_y[BB * NH * DIN];
__device__ float g_av[BB * DM];
__device__ float g_part[2097152];               // 8 MB split-K partials

typedef unsigned long long ull;

// ---------------- f32x2 packed-FMA helpers (used in scores/wsum only) ----------------
__device__ __forceinline__ ull pk2(float lo, float hi) {
    ull r;
    asm("mov.b64 %0, {%1, %2};" : "=l"(r) : "f"(lo), "f"(hi));
    return r;
}
__device__ __forceinline__ ull ff2(ull a, ull b, ull c) {
    ull d;
    asm("fma.rn.f32x2 %0, %1, %2, %3;" : "=l"(d) : "l"(a), "l"(b), "l"(c));
    return d;
}
__device__ __forceinline__ void up2(float& lo, float& hi, ull a) {
    asm("mov.b64 {%0, %1}, %2;" : "=f"(lo), "=f"(hi) : "l"(a));
}

// ---------------- fused 16-row dense: out[16][1024] = X[16][K] @ W[K][1024] + bias
// grid 64 (j-chunks of 16), block 256 = (16 j-lanes x 16 K-splits)
template <int K>
__global__ void k_dense16(const float* __restrict__ X, const float* __restrict__ W,
                          const float* __restrict__ bias, float* __restrict__ out) {
    __shared__ float xs[256][17];
    __shared__ float ps[16][256];
    int tid = threadIdx.x;
    int jl = tid & 15, ks = tid >> 4;
    int j = blockIdx.x * 16 + jl;
    float acc[BB];
#pragma unroll
    for (int b = 0; b < BB; ++b) acc[b] = 0.f;

    for (int k0 = 0; k0 < K; k0 += 256) {
        __syncthreads();
#pragma unroll
        for (int i = 0; i < 16; ++i) {
            int l = tid + i * 256;
            int k = l & 255, b = l >> 8;
            xs[k][b] = X[b * K + k0 + k];
        }
        __syncthreads();
#pragma unroll 8
        for (int kk = ks * 16; kk < ks * 16 + 16; ++kk) {
            float w = W[(size_t)(k0 + kk) * DM + j];
#pragma unroll
            for (int b = 0; b < BB; ++b) acc[b] += w * xs[kk][b];
        }
    }
#pragma unroll
    for (int b = 0; b < BB; ++b) ps[ks][b * 16 + jl] = acc[b];
    __syncthreads();
    {
        int b = tid >> 4, jj = tid & 15;
        float s = 0.f;
#pragma unroll
        for (int z = 0; z < 16; ++z) s += ps[z][tid];
        out[b * DM + blockIdx.x * 16 + jj] = s + bias[blockIdx.x * 16 + jj];
    }
}

// ---------------- t[b,h,j] = sum_d Wk[j, h*64+d] * q[b, h*64+d]
// grid (16 h, 8 j-chunks of 128), block 128 = (32 j-lanes x 4 b-groups)
__global__ void k_t(const float* __restrict__ Wk) {
    int h = blockIdx.x, j0 = blockIdx.y * 128;
    int tid = threadIdx.x;
    int jl = tid & 31, bg = tid >> 5;
    __shared__ float qs[BB][HD];
    __shared__ float wk[32][65];
    for (int l = tid; l < BB * HD; l += 128) {
        int b = l >> 6, d = l & 63;
        qs[b][d] = g_q[b * DM + h * HD + d];
    }
    for (int st = 0; st < 4; ++st) {
        __syncthreads();
#pragma unroll
        for (int i = 0; i < 16; ++i) {
            int l = tid + i * 128;
            int r = l >> 6, d = l & 63;
            wk[r][d] = Wk[(size_t)(j0 + st * 32 + r) * DM + h * HD + d];
        }
        __syncthreads();
        float acc[4] = {0.f, 0.f, 0.f, 0.f};
#pragma unroll 8
        for (int d = 0; d < HD; ++d) {
            float w = wk[jl][d];
#pragma unroll
            for (int bb = 0; bb < 4; ++bb) acc[bb] += w * qs[bg * 4 + bb][d];
        }
        int j = j0 + st * 32 + jl;
#pragma unroll
        for (int bb = 0; bb < 4; ++bb)
            g_t[(size_t)((bg * 4 + bb) * NH + h) * DM + j] = acc[bb];
    }
}

// ---------------- tiled split-K GEMM (round-4 proven version):
// C[M,N] = A[M,K] @ B ; B is [N,K] (kmajor) or [K,N]
template <int MM, int NN, int KK, int SPLITS, bool BKMAJOR>
__global__ void k_gemm(const float* __restrict__ A, const float* __restrict__ Bm,
                       float* __restrict__ part) {
    constexpr int KC = KK / SPLITS;
    int n0 = blockIdx.x * 64, m0 = blockIdx.y * 64, k0 = blockIdx.z * KC;
    __shared__ float Asm[16][64];
    __shared__ float Bsm[16][64];
    int tid = threadIdx.x;
    int tx = tid & 15, ty = tid >> 4;
    float acc[4][4] = {};
    for (int kt = 0; kt < KC; kt += 16) {
        {
            int m = tid >> 2, kq = tid & 3;
            float4 a4 = *(const float4*)(A + (size_t)(m0 + m) * KK + k0 + kt + kq * 4);
            Asm[kq * 4 + 0][m] = a4.x; Asm[kq * 4 + 1][m] = a4.y;
            Asm[kq * 4 + 2][m] = a4.z; Asm[kq * 4 + 3][m] = a4.w;
        }
        if constexpr (BKMAJOR) {
            int n = tid >> 2, kq = tid & 3;
            float4 b4 = *(const float4*)(Bm + (size_t)(n0 + n) * KK + k0 + kt + kq * 4);
            Bsm[kq * 4 + 0][n] = b4.x; Bsm[kq * 4 + 1][n] = b4.y;
            Bsm[kq * 4 + 2][n] = b4.z; Bsm[kq * 4 + 3][n] = b4.w;
        } else {
            int kk = tid >> 4, n4 = tid & 15;
            float4 b4 = *(const float4*)(Bm + (size_t)(k0 + kt + kk) * NN + n0 + n4 * 4);
            *(float4*)&Bsm[kk][n4 * 4] = b4;
        }
        __syncthreads();
#pragma unroll
        for (int kk = 0; kk < 16; ++kk) {
            float4 a = *(const float4*)&Asm[kk][ty * 4];
            float4 b = *(const float4*)&Bsm[kk][tx * 4];
            acc[0][0] += a.x * b.x; acc[0][1] += a.x * b.y; acc[0][2] += a.x * b.z; acc[0][3] += a.x * b.w;
            acc[1][0] += a.y * b.x; acc[1][1] += a.y * b.y; acc[1][2] += a.y * b.z; acc[1][3] += a.y * b.w;
            acc[2][0] += a.z * b.x; acc[2][1] += a.z * b.y; acc[2][2] += a.z * b.z; acc[2][3] += a.z * b.w;
            acc[3][0] += a.w * b.x; acc[3][1] += a.w * b.y; acc[3][2] += a.w * b.z; acc[3][3] += a.w * b.w;
        }
        __syncthreads();
    }
    float* p = part + (size_t)blockIdx.z * MM * NN;
#pragma unroll
    for (int i = 0; i < 4; ++i) {
        float4 v = make_float4(acc[i][0], acc[i][1], acc[i][2], acc[i][3]);
        *(float4*)(p + (size_t)(m0 + ty * 4 + i) * NN + n0 + tx * 4) = v;
    }
}

// ---------------- reduce u partials (16 splits) and write transposed g_uT[b][i][h]
__global__ void k_reduce_ut(const float* __restrict__ part) {
    int e = blockIdx.x * 256 + threadIdx.x;  // 131072 total
    float s = 0.f;
#pragma unroll
    for (int z = 0; z < 16; ++z) s += part[(size_t)z * 131072 + e];
    int m = e >> 9, n = e & 511;
    int b = m >> 4, h = m & 15;
    g_uT[(size_t)(b * DIN + n) * NH + h] = s;
}

// ---------------- scores (round-4 loop): g_scores[b,h,s] = exp((x2[b,s,:].u[b,h,:]) / 8)
// grid (16 b, 32 s-chunks of 128), block 128 (one s-row per thread); j-slab 16
__global__ void k_scores(const float* __restrict__ x2) {
    int b = blockIdx.x;
    int s0 = blockIdx.y * 128;
    __shared__ float uT[DIN][16];  // 32 KB; inner reads are same-address broadcasts
    __shared__ float xs[128][17];  // 8.7 KB; read stride 17 -> conflict-free
    int tid = threadIdx.x;
    for (int l = tid; l < DIN * NH; l += 128) {
        uT[l >> 4][l & 15] = g_uT[(size_t)b * DIN * NH + l];
    }
    ull acc[8];
#pragma unroll
    for (int p = 0; p < 8; ++p) acc[p] = 0ull;
    const float* x2b = x2 + ((size_t)b * SS + s0) * DIN;
    for (int j0 = 0; j0 < DIN; j0 += 16) {
        __syncthreads();  // first iter also publishes uT
#pragma unroll
        for (int v = 0; v < 4; ++v) {
            int f = tid + v * 128;          // float4 index 0..511
            int rr = f >> 2, jq = f & 3;
            float4 xv = *(const float4*)(x2b + (size_t)rr * DIN + j0 + jq * 4);
            xs[rr][jq * 4 + 0] = xv.x; xs[rr][jq * 4 + 1] = xv.y;
            xs[rr][jq * 4 + 2] = xv.z; xs[rr][jq * 4 + 3] = xv.w;
        }
        __syncthreads();
#pragma unroll
        for (int jj = 0; jj < 16; ++jj) {
            float xv = xs[tid][jj];
            ull xd = pk2(xv, xv);
            const ulonglong2* up = (const ulonglong2*)&uT[j0 + jj][0];
            ulonglong2 u01 = up[0], u23 = up[1], u45 = up[2], u67 = up[3];
            acc[0] = ff2(xd, u01.x, acc[0]);
            acc[1] = ff2(xd, u01.y, acc[1]);
            acc[2] = ff2(xd, u23.x, acc[2]);
            acc[3] = ff2(xd, u23.y, acc[3]);
            acc[4] = ff2(xd, u45.x, acc[4]);
            acc[5] = ff2(xd, u45.y, acc[5]);
            acc[6] = ff2(xd, u67.x, acc[6]);
            acc[7] = ff2(xd, u67.y, acc[7]);
        }
    }
#pragma unroll
    for (int p = 0; p < 8; ++p) {
        float lo, hi;
        up2(lo, hi, acc[p]);
        g_scores[((size_t)(b * NH + 2 * p) << 12) + s0 + tid]     = __expf(lo * 0.125f);
        g_scores[((size_t)(b * NH + 2 * p + 1) << 12) + s0 + tid] = __expf(hi * 0.125f);
    }
}

// ---------------- weighted-sum partials + per-chunk sumexp (round-4 loop)
// grid (16 b, 32 s-chunks of 128), block 128 (4 d per thread)
__global__ void k_wsum(const float* __restrict__ x3) {
    int b = blockIdx.x, c = blockIdx.y;
    int s0 = c * 128;
    __shared__ float at[128][20];  // [s][h pad] rows 80B -> 16B aligned
    int tid = threadIdx.x;
    for (int l = tid; l < NH * 128; l += 128) {
        int h = l >> 7, s = l & 127;
        at[s][h] = g_scores[((size_t)(b * NH + h) << 12) + s0 + s];
    }
    __syncthreads();
    if (tid < NH) {  // per-chunk sumexp partial (fixed order, deterministic)
        float s = 0.f;
#pragma unroll 8
        for (int i = 0; i < 128; ++i) s += at[i][tid];
        g_wsump[(c * BB + b) * NH + tid] = s;
    }
    ull acc[8][4];
#pragma unroll
    for (int p = 0; p < 8; ++p)
#pragma unroll
        for (int d = 0; d < 4; ++d) acc[p][d] = 0ull;
    int d0 = tid * 4;
    const float* x3b = x3 + ((size_t)b * SS + s0) * DIN + d0;
#pragma unroll 4
    for (int s = 0; s < 128; ++s) {
        float4 xv = *(const float4*)(x3b + (size_t)s * DIN);
        ull xd[4];
        xd[0] = pk2(xv.x, xv.x); xd[1] = pk2(xv.y, xv.y);
        xd[2] = pk2(xv.z, xv.z); xd[3] = pk2(xv.w, xv.w);
        const ulonglong2* wp = (const ulonglong2*)&at[s][0];
        ulonglong2 wA = wp[0], wB = wp[1], wC = wp[2], wD = wp[3];
        ull w[8] = {wA.x, wA.y, wB.x, wB.y, wC.x, wC.y, wD.x, wD.y};
#pragma unroll
        for (int p = 0; p < 8; ++p) {
#pragma unroll
            for (int d = 0; d < 4; ++d) acc[p][d] = ff2(xd[d], w[p], acc[p][d]);
        }
    }
    float* yp = g_ypart + ((size_t)(c * BB + b) * NH) * DIN;
#pragma unroll
    for (int p = 0; p < 8; ++p) {
        float lo[4], hi[4];
#pragma unroll
        for (int d = 0; d < 4; ++d) up2(lo[d], hi[d], acc[p][d]);
        *(float4*)(yp + (2 * p) * DIN + d0)     = make_float4(lo[0], lo[1], lo[2], lo[3]);
        *(float4*)(yp + (2 * p + 1) * DIN + d0) = make_float4(hi[0], hi[1], hi[2], hi[3]);
    }
}

// ---------------- y = (sum over chunks ypart) / (sum over chunks sumexp)
__global__ void k_reduce_norm() {
    int e = blockIdx.x * 256 + threadIdx.x;  // 131072
    int bh = e >> 9;
    float s = 0.f, w = 0.f;
#pragma unroll
    for (int c = 0; c < 32; ++c) {
        s += g_ypart[(size_t)c * 131072 + e];
        w += g_wsump[c * 256 + bh];
    }
    g_y[e] = s / w;
}

// ---------------- av[b, h*64+d] = sum_j (Σ ye_parts + be2)[j] * Wv[j, h*64+d] + bv
__global__ void k_av(const float* __restrict__ part, const float* __restrict__ be2,
                     const float* __restrict__ Wv, const float* __restrict__ bv) {
    int b = blockIdx.x, h = blockIdx.y;
    int d = threadIdx.x & 63, jq = threadIdx.x >> 6;
    __shared__ float yes[DM];
    __shared__ float red[4][64];
    for (int l = threadIdx.x; l < DM; l += 256) {
        float s = be2[l];
#pragma unroll
        for (int z = 0; z < 8; ++z) s += part[(size_t)z * 262144 + (size_t)(b * NH + h) * DM + l];
        yes[l] = s;
    }
    __syncthreads();
    float acc = 0.f;
    const float* wp = Wv + h * HD + d;
#pragma unroll 8
    for (int j = jq * 256; j < jq * 256 + 256; ++j) acc += yes[j] * wp[(size_t)j * DM];
    red[jq][d] = acc;
    __syncthreads();
    if (jq == 0) {
        float s = red[0][d] + red[1][d] + red[2][d] + red[3][d] + bv[h * HD + d];
        g_av[b * DM + h * HD + d] = s;
    }
}

// ---------------- launch ----------------
extern "C" void kernel_launch(void* const* d_in, const int* in_sizes, int n_in,
                              void* d_out, int out_size) {
    const float* x1  = (const float*)d_in[0];
    const float* x2  = (const float*)d_in[1];
    const float* x3  = (const float*)d_in[2];
    const float* We1 = (const float*)d_in[3];
    const float* be1 = (const float*)d_in[4];
    const float* We2 = (const float*)d_in[5];
    const float* be2 = (const float*)d_in[6];
    const float* Wq  = (const float*)d_in[7];
    const float* bq  = (const float*)d_in[8];
    const float* Wk  = (const float*)d_in[9];
    // d_in[10] = bk: cancels in normalization, exactly dropped
    const float* Wv  = (const float*)d_in[11];
    const float* bv  = (const float*)d_in[12];
    const float* Wo  = (const float*)d_in[13];
    const float* bo  = (const float*)d_in[14];
    float* out = (float*)d_out;

    float *pg_part, *pg_x1e, *pg_q, *pg_t, *pg_y, *pg_av;
    cudaGetSymbolAddress((void**)&pg_part, g_part);
    cudaGetSymbolAddress((void**)&pg_x1e,  g_x1e);
    cudaGetSymbolAddress((void**)&pg_q,    g_q);
    cudaGetSymbolAddress((void**)&pg_t,    g_t);
    cudaGetSymbolAddress((void**)&pg_y,    g_y);
    cudaGetSymbolAddress((void**)&pg_av,   g_av);

    // 1) x1e = x1 @ We1 + be1
    k_dense16<512><<<64, 256>>>(x1, We1, be1, pg_x1e);
    // 2) q = x1e @ Wq + bq
    k_dense16<1024><<<64, 256>>>(pg_x1e, Wq, bq, pg_q);
    // 3) t[b,h,j] = Wk_h @ q_h
    k_t<<<dim3(NH, 8), 128>>>(Wk);
    // 4) u = t @ We2^T  -> transposed g_uT
    k_gemm<256, 512, 1024, 16, true><<<dim3(8, 4, 16), 256>>>(pg_t, We2, pg_part);
    k_reduce_ut<<<512, 256>>>(pg_part);
    // 5) unnormalized exp scores (softmax max-shift dropped; normalization deferred)
    k_scores<<<dim3(BB, 32), 128>>>(x2);
    // 6) weighted sums + sumexp partials, then normalize into g_y
    k_wsum<<<dim3(BB, 32), 128>>>(x3);
    k_reduce_norm<<<512, 256>>>();
    // 7) ye partials = y @ We2   (be2 + reduction folded into k_av)
    k_gemm<256, 1024, 512, 8, false><<<dim3(16, 4, 8), 256>>>(pg_y, We2, pg_part);
    // 8) av = per-head (Σ ye_parts + be2) @ Wv_h + bv
    k_av<<<dim3(BB, NH), 256>>>(pg_part, be2, Wv, bv);
    // 9) out = av @ Wo + bo
    k_dense16<1024><<<64, 256>>>(pg_av, Wo, bo, out);
}

// round 7
// speedup vs baseline: 1.4051x; 1.0413x over previous
#include <cuda_runtime.h>
#include <cstddef>

#define BB   16
#define SS   4096
#define DIN  512
#define DM   1024
#define NH   16
#define HD   64

// ---------------- scratch (no allocations allowed) ----------------
__device__ float g_x1e[BB * DM];
__device__ float g_q[BB * DM];
__device__ float g_t[BB * NH * DM];             // 1 MB
__device__ float g_uT[BB * DIN * NH];           // 0.5 MB, [b][i][h]
__device__ float g_ypart[32 * BB * NH * DIN];   // 16.8 MB, [c][b][h][d]
__device__ float g_wsump[32 * BB * NH];         // per-chunk sum of exp
__device__ float g_y[BB * NH * DIN];
__device__ float g_av[BB * DM];
__device__ float g_part[4194304];               // 16 MB split-K partials

typedef unsigned long long ull;

// ---------------- f32x2 packed-FMA helpers ----------------
__device__ __forceinline__ ull pk2(float lo, float hi) {
    ull r;
    asm("mov.b64 %0, {%1, %2};" : "=l"(r) : "f"(lo), "f"(hi));
    return r;
}
__device__ __forceinline__ ull ff2(ull a, ull b, ull c) {
    ull d;
    asm("fma.rn.f32x2 %0, %1, %2, %3;" : "=l"(d) : "l"(a), "l"(b), "l"(c));
    return d;
}
__device__ __forceinline__ void up2(float& lo, float& hi, ull a) {
    asm("mov.b64 {%0, %1}, %2;" : "=f"(lo), "=f"(hi) : "l"(a));
}

// ---------------- fused 16-row dense: out[16][1024] = X[16][K] @ W[K][1024] + bias
template <int K>
__global__ void k_dense16(const float* __restrict__ X, const float* __restrict__ W,
                          const float* __restrict__ bias, float* __restrict__ out) {
    __shared__ float xs[256][17];
    __shared__ float ps[16][256];
    int tid = threadIdx.x;
    int jl = tid & 15, ks = tid >> 4;
    int j = blockIdx.x * 16 + jl;
    float acc[BB];
#pragma unroll
    for (int b = 0; b < BB; ++b) acc[b] = 0.f;

    for (int k0 = 0; k0 < K; k0 += 256) {
        __syncthreads();
#pragma unroll
        for (int i = 0; i < 16; ++i) {
            int l = tid + i * 256;
            int k = l & 255, b = l >> 8;
            xs[k][b] = X[b * K + k0 + k];
        }
        __syncthreads();
#pragma unroll 8
        for (int kk = ks * 16; kk < ks * 16 + 16; ++kk) {
            float w = W[(size_t)(k0 + kk) * DM + j];
#pragma unroll
            for (int b = 0; b < BB; ++b) acc[b] += w * xs[kk][b];
        }
    }
#pragma unroll
    for (int b = 0; b < BB; ++b) ps[ks][b * 16 + jl] = acc[b];
    __syncthreads();
    {
        int b = tid >> 4, jj = tid & 15;
        float s = 0.f;
#pragma unroll
        for (int z = 0; z < 16; ++z) s += ps[z][tid];
        out[b * DM + blockIdx.x * 16 + jj] = s + bias[blockIdx.x * 16 + jj];
    }
}

// ---------------- t[b,h,j] = sum_d Wk[j, h*64+d] * q[b, h*64+d]
__global__ void k_t(const float* __restrict__ Wk) {
    int h = blockIdx.x, j0 = blockIdx.y * 128;
    int tid = threadIdx.x;
    int jl = tid & 31, bg = tid >> 5;
    __shared__ float qs[BB][HD];
    __shared__ float wk[32][65];
    for (int l = tid; l < BB * HD; l += 128) {
        int b = l >> 6, d = l & 63;
        qs[b][d] = g_q[b * DM + h * HD + d];
    }
    for (int st = 0; st < 4; ++st) {
        __syncthreads();
#pragma unroll
        for (int i = 0; i < 16; ++i) {
            int l = tid + i * 128;
            int r = l >> 6, d = l & 63;
            wk[r][d] = Wk[(size_t)(j0 + st * 32 + r) * DM + h * HD + d];
        }
        __syncthreads();
        float acc[4] = {0.f, 0.f, 0.f, 0.f};
#pragma unroll 8
        for (int d = 0; d < HD; ++d) {
            float w = wk[jl][d];
#pragma unroll
            for (int bb = 0; bb < 4; ++bb) acc[bb] += w * qs[bg * 4 + bb][d];
        }
        int j = j0 + st * 32 + jl;
#pragma unroll
        for (int bb = 0; bb < 4; ++bb)
            g_t[(size_t)((bg * 4 + bb) * NH + h) * DM + j] = acc[bb];
    }
}

// ---------------- tiled split-K GEMM (proven version):
// C[M,N] = A[M,K] @ B ; B is [N,K] (kmajor) or [K,N]
template <int MM, int NN, int KK, int SPLITS, bool BKMAJOR>
__global__ void k_gemm(const float* __restrict__ A, const float* __restrict__ Bm,
                       float* __restrict__ part) {
    constexpr int KC = KK / SPLITS;
    int n0 = blockIdx.x * 64, m0 = blockIdx.y * 64, k0 = blockIdx.z * KC;
    __shared__ float Asm[16][64];
    __shared__ float Bsm[16][64];
    int tid = threadIdx.x;
    int tx = tid & 15, ty = tid >> 4;
    float acc[4][4] = {};
    for (int kt = 0; kt < KC; kt += 16) {
        {
            int m = tid >> 2, kq = tid & 3;
            float4 a4 = *(const float4*)(A + (size_t)(m0 + m) * KK + k0 + kt + kq * 4);
            Asm[kq * 4 + 0][m] = a4.x; Asm[kq * 4 + 1][m] = a4.y;
            Asm[kq * 4 + 2][m] = a4.z; Asm[kq * 4 + 3][m] = a4.w;
        }
        if constexpr (BKMAJOR) {
            int n = tid >> 2, kq = tid & 3;
            float4 b4 = *(const float4*)(Bm + (size_t)(n0 + n) * KK + k0 + kt + kq * 4);
            Bsm[kq * 4 + 0][n] = b4.x; Bsm[kq * 4 + 1][n] = b4.y;
            Bsm[kq * 4 + 2][n] = b4.z; Bsm[kq * 4 + 3][n] = b4.w;
        } else {
            int kk = tid >> 4, n4 = tid & 15;
            float4 b4 = *(const float4*)(Bm + (size_t)(k0 + kt + kk) * NN + n0 + n4 * 4);
            *(float4*)&Bsm[kk][n4 * 4] = b4;
        }
        __syncthreads();
#pragma unroll
        for (int kk = 0; kk < 16; ++kk) {
            float4 a = *(const float4*)&Asm[kk][ty * 4];
            float4 b = *(const float4*)&Bsm[kk][tx * 4];
            acc[0][0] += a.x * b.x; acc[0][1] += a.x * b.y; acc[0][2] += a.x * b.z; acc[0][3] += a.x * b.w;
            acc[1][0] += a.y * b.x; acc[1][1] += a.y * b.y; acc[1][2] += a.y * b.z; acc[1][3] += a.y * b.w;
            acc[2][0] += a.z * b.x; acc[2][1] += a.z * b.y; acc[2][2] += a.z * b.z; acc[2][3] += a.z * b.w;
            acc[3][0] += a.w * b.x; acc[3][1] += a.w * b.y; acc[3][2] += a.w * b.z; acc[3][3] += a.w * b.w;
        }
        __syncthreads();
    }
    float* p = part + (size_t)blockIdx.z * MM * NN;
#pragma unroll
    for (int i = 0; i < 4; ++i) {
        float4 v = make_float4(acc[i][0], acc[i][1], acc[i][2], acc[i][3]);
        *(float4*)(p + (size_t)(m0 + ty * 4 + i) * NN + n0 + tx * 4) = v;
    }
}

// ---------------- reduce u partials (32 splits) and write transposed g_uT[b][i][h]
__global__ void k_reduce_ut(const float* __restrict__ part) {
    int e = blockIdx.x * 256 + threadIdx.x;  // 131072 total
    float s = 0.f;
#pragma unroll
    for (int z = 0; z < 32; ++z) s += part[(size_t)z * 131072 + e];
    int m = e >> 9, n = e & 511;
    int b = m >> 4, h = m & 15;
    g_uT[(size_t)(b * DIN + n) * NH + h] = s;
}

// ---------------- FUSED attention: scores (exp, unnormalized) + weighted sum, per (b, s-chunk)
// grid (16 b, 32 chunks of 128 s), block 128
__global__ void k_attn(const float* __restrict__ x2, const float* __restrict__ x3) {
    int b = blockIdx.x, c = blockIdx.y;
    int s0 = c * 128;
    __shared__ __align__(16) float sbuf[DIN * NH];  // 32 KB: phase1 uT[512][16], phase2 at[128][20]
    __shared__ float xs[128][17];                   // 8.7 KB staging, conflict-free reads
    int tid = threadIdx.x;

    // ---- phase 1: scores for this chunk (identical loop to proven k_scores) ----
    float (*uT)[NH] = (float(*)[NH])sbuf;
    for (int l = tid; l < DIN * NH; l += 128) sbuf[l] = g_uT[(size_t)b * DIN * NH + l];
    ull acc[8];
#pragma unroll
    for (int p = 0; p < 8; ++p) acc[p] = 0ull;
    const float* x2b = x2 + ((size_t)b * SS + s0) * DIN;
    for (int j0 = 0; j0 < DIN; j0 += 16) {
        __syncthreads();  // first iter also publishes uT
#pragma unroll
        for (int v = 0; v < 4; ++v) {
            int f = tid + v * 128;          // float4 index 0..511
            int rr = f >> 2, jq = f & 3;
            float4 xv = *(const float4*)(x2b + (size_t)rr * DIN + j0 + jq * 4);
            xs[rr][jq * 4 + 0] = xv.x; xs[rr][jq * 4 + 1] = xv.y;
            xs[rr][jq * 4 + 2] = xv.z; xs[rr][jq * 4 + 3] = xv.w;
        }
        __syncthreads();
#pragma unroll
        for (int jj = 0; jj < 16; ++jj) {
            float xv = xs[tid][jj];
            ull xd = pk2(xv, xv);
            const ulonglong2* up = (const ulonglong2*)&uT[j0 + jj][0];
            ulonglong2 u01 = up[0], u23 = up[1], u45 = up[2], u67 = up[3];
            acc[0] = ff2(xd, u01.x, acc[0]);
            acc[1] = ff2(xd, u01.y, acc[1]);
            acc[2] = ff2(xd, u23.x, acc[2]);
            acc[3] = ff2(xd, u23.y, acc[3]);
            acc[4] = ff2(xd, u45.x, acc[4]);
            acc[5] = ff2(xd, u45.y, acc[5]);
            acc[6] = ff2(xd, u67.x, acc[6]);
            acc[7] = ff2(xd, u67.y, acc[7]);
        }
    }
    // exp weights -> smem at[s][h] (aliased over uT region; barrier first)
    float ex[NH];
#pragma unroll
    for (int p = 0; p < 8; ++p) {
        float lo, hi;
        up2(lo, hi, acc[p]);
        ex[2 * p]     = __expf(lo * 0.125f);
        ex[2 * p + 1] = __expf(hi * 0.125f);
    }
    __syncthreads();  // all done reading uT
    float (*at)[20] = (float(*)[20])sbuf;  // 128x20 = 10240 floats? no: 2560 floats, fits
#pragma unroll
    for (int h = 0; h < NH; ++h) at[tid][h] = ex[h];
    __syncthreads();

    // ---- per-chunk sumexp partial (fixed order, deterministic) ----
    if (tid < NH) {
        float s = 0.f;
#pragma unroll 8
        for (int i = 0; i < 128; ++i) s += at[i][tid];
        g_wsump[(c * BB + b) * NH + tid] = s;
    }

    // ---- phase 2: weighted sum (identical loop to proven k_wsum) ----
    ull wacc[8][4];
#pragma unroll
    for (int p = 0; p < 8; ++p)
#pragma unroll
        for (int d = 0; d < 4; ++d) wacc[p][d] = 0ull;
    int d0 = tid * 4;
    const float* x3b = x3 + ((size_t)b * SS + s0) * DIN + d0;
#pragma unroll 4
    for (int s = 0; s < 128; ++s) {
        float4 xv = *(const float4*)(x3b + (size_t)s * DIN);
        ull xd[4];
        xd[0] = pk2(xv.x, xv.x); xd[1] = pk2(xv.y, xv.y);
        xd[2] = pk2(xv.z, xv.z); xd[3] = pk2(xv.w, xv.w);
        const ulonglong2* wp = (const ulonglong2*)&at[s][0];
        ulonglong2 wA = wp[0], wB = wp[1], wC = wp[2], wD = wp[3];
        ull w[8] = {wA.x, wA.y, wB.x, wB.y, wC.x, wC.y, wD.x, wD.y};
#pragma unroll
        for (int p = 0; p < 8; ++p) {
#pragma unroll
            for (int d = 0; d < 4; ++d) wacc[p][d] = ff2(xd[d], w[p], wacc[p][d]);
        }
    }
    float* yp = g_ypart + ((size_t)(c * BB + b) * NH) * DIN;
#pragma unroll
    for (int p = 0; p < 8; ++p) {
        float lo[4], hi[4];
#pragma unroll
        for (int d = 0; d < 4; ++d) up2(lo[d], hi[d], wacc[p][d]);
        *(float4*)(yp + (2 * p) * DIN + d0)     = make_float4(lo[0], lo[1], lo[2], lo[3]);
        *(float4*)(yp + (2 * p + 1) * DIN + d0) = make_float4(hi[0], hi[1], hi[2], hi[3]);
    }
}

// ---------------- y = (sum over chunks ypart) / (sum over chunks sumexp)
__global__ void k_reduce_norm() {
    int e = blockIdx.x * 256 + threadIdx.x;  // 131072
    int bh = e >> 9;
    float s = 0.f, w = 0.f;
#pragma unroll
    for (int c = 0; c < 32; ++c) {
        s += g_ypart[(size_t)c * 131072 + e];
        w += g_wsump[c * 256 + bh];
    }
    g_y[e] = s / w;
}

// ---------------- av[b, h*64+d] = sum_j (Σ ye_parts + be2)[j] * Wv[j, h*64+d] + bv
__global__ void k_av(const float* __restrict__ part, const float* __restrict__ be2,
                     const float* __restrict__ Wv, const float* __restrict__ bv) {
    int b = blockIdx.x, h = blockIdx.y;
    int d = threadIdx.x & 63, jq = threadIdx.x >> 6;
    __shared__ float yes[DM];
    __shared__ float red[4][64];
    for (int l = threadIdx.x; l < DM; l += 256) {
        float s = be2[l];
#pragma unroll
        for (int z = 0; z < 16; ++z) s += part[(size_t)z * 262144 + (size_t)(b * NH + h) * DM + l];
        yes[l] = s;
    }
    __syncthreads();
    float acc = 0.f;
    const float* wp = Wv + h * HD + d;
#pragma unroll 8
    for (int j = jq * 256; j < jq * 256 + 256; ++j) acc += yes[j] * wp[(size_t)j * DM];
    red[jq][d] = acc;
    __syncthreads();
    if (jq == 0) {
        float s = red[0][d] + red[1][d] + red[2][d] + red[3][d] + bv[h * HD + d];
        g_av[b * DM + h * HD + d] = s;
    }
}

// ---------------- launch ----------------
extern "C" void kernel_launch(void* const* d_in, const int* in_sizes, int n_in,
                              void* d_out, int out_size) {
    const float* x1  = (const float*)d_in[0];
    const float* x2  = (const float*)d_in[1];
    const float* x3  = (const float*)d_in[2];
    const float* We1 = (const float*)d_in[3];
    const float* be1 = (const float*)d_in[4];
    const float* We2 = (const float*)d_in[5];
    const float* be2 = (const float*)d_in[6];
    const float* Wq  = (const float*)d_in[7];
    const float* bq  = (const float*)d_in[8];
    const float* Wk  = (const float*)d_in[9];
    // d_in[10] = bk: cancels in normalization, exactly dropped
    const float* Wv  = (const float*)d_in[11];
    const float* bv  = (const float*)d_in[12];
    const float* Wo  = (const float*)d_in[13];
    const float* bo  = (const float*)d_in[14];
    float* out = (float*)d_out;

    float *pg_part, *pg_x1e, *pg_q, *pg_t, *pg_y, *pg_av;
    cudaGetSymbolAddress((void**)&pg_part, g_part);
    cudaGetSymbolAddress((void**)&pg_x1e,  g_x1e);
    cudaGetSymbolAddress((void**)&pg_q,    g_q);
    cudaGetSymbolAddress((void**)&pg_t,    g_t);
    cudaGetSymbolAddress((void**)&pg_y,    g_y);
    cudaGetSymbolAddress((void**)&pg_av,   g_av);

    // 1) x1e = x1 @ We1 + be1
    k_dense16<512><<<64, 256>>>(x1, We1, be1, pg_x1e);
    // 2) q = x1e @ Wq + bq
    k_dense16<1024><<<64, 256>>>(pg_x1e, Wq, bq, pg_q);
    // 3) t[b,h,j] = Wk_h @ q_h
    k_t<<<dim3(NH, 8), 128>>>(Wk);
    // 4) u = t @ We2^T  -> transposed g_uT  (32-way split-K, 1024 blocks)
    k_gemm<256, 512, 1024, 32, true><<<dim3(8, 4, 32), 256>>>(pg_t, We2, pg_part);
    k_reduce_ut<<<512, 256>>>(pg_part);
    // 5) FUSED scores + weighted-sum + sumexp (no global score tensor)
    k_attn<<<dim3(BB, 32), 128>>>(x2, x3);
    // 6) normalize into g_y
    k_reduce_norm<<<512, 256>>>();
    // 7) ye partials = y @ We2   (16-way split-K; be2 + reduction folded into k_av)
    k_gemm<256, 1024, 512, 16, false><<<dim3(16, 4, 16), 256>>>(pg_y, We2, pg_part);
    // 8) av = per-head (Σ ye_parts + be2) @ Wv_h + bv
    k_av<<<dim3(BB, NH), 256>>>(pg_part, be2, Wv, bv);
    // 9) out = av @ Wo + bo
    k_dense16<1024><<<64, 256>>>(pg_av, Wo, bo, out);
}

// round 8
// speedup vs baseline: 1.4380x; 1.0234x over previous
#include <cuda_runtime.h>
#include <cstddef>

#define BB   16
#define SS   4096
#define DIN  512
#define DM   1024
#define NH   16
#define HD   64

// ---------------- scratch (no allocations allowed) ----------------
__device__ float g_x1e[BB * DM];
__device__ float g_q[BB * DM];
__device__ float g_t[BB * NH * DM];             // 1 MB
__device__ float g_uT[BB * DIN * NH];           // 0.5 MB, [b][i][h]
__device__ float g_ypart[32 * BB * NH * DIN];   // 16.8 MB, [c][b][h][d]
__device__ float g_wsump[32 * BB * NH];         // per-chunk sum of exp
__device__ float g_y[BB * NH * DIN];
__device__ float g_av[BB * DM];
__device__ float g_part[4194304];               // 16 MB split-K partials

typedef unsigned long long ull;

// ---------------- f32x2 packed-FMA helpers (attention kernels only) ----------------
__device__ __forceinline__ ull pk2(float lo, float hi) {
    ull r;
    asm("mov.b64 %0, {%1, %2};" : "=l"(r) : "f"(lo), "f"(hi));
    return r;
}
__device__ __forceinline__ ull ff2(ull a, ull b, ull c) {
    ull d;
    asm("fma.rn.f32x2 %0, %1, %2, %3;" : "=l"(d) : "l"(a), "l"(b), "l"(c));
    return d;
}
__device__ __forceinline__ void up2(float& lo, float& hi, ull a) {
    asm("mov.b64 {%0, %1}, %2;" : "=f"(lo), "=f"(hi) : "l"(a));
}

// ---------------- fused 16-row dense: out[16][1024] = X[16][K] @ W[K][1024] + bias
template <int K>
__global__ void k_dense16(const float* __restrict__ X, const float* __restrict__ W,
                          const float* __restrict__ bias, float* __restrict__ out) {
    __shared__ float xs[256][17];
    __shared__ float ps[16][256];
    int tid = threadIdx.x;
    int jl = tid & 15, ks = tid >> 4;
    int j = blockIdx.x * 16 + jl;
    float acc[BB];
#pragma unroll
    for (int b = 0; b < BB; ++b) acc[b] = 0.f;

    for (int k0 = 0; k0 < K; k0 += 256) {
        __syncthreads();
#pragma unroll
        for (int i = 0; i < 16; ++i) {
            int l = tid + i * 256;
            int k = l & 255, b = l >> 8;
            xs[k][b] = X[b * K + k0 + k];
        }
        __syncthreads();
#pragma unroll 8
        for (int kk = ks * 16; kk < ks * 16 + 16; ++kk) {
            float w = W[(size_t)(k0 + kk) * DM + j];
#pragma unroll
            for (int b = 0; b < BB; ++b) acc[b] += w * xs[kk][b];
        }
    }
#pragma unroll
    for (int b = 0; b < BB; ++b) ps[ks][b * 16 + jl] = acc[b];
    __syncthreads();
    {
        int b = tid >> 4, jj = tid & 15;
        float s = 0.f;
#pragma unroll
        for (int z = 0; z < 16; ++z) s += ps[z][tid];
        out[b * DM + blockIdx.x * 16 + jj] = s + bias[blockIdx.x * 16 + jj];
    }
}

// ---------------- t[b,h,j] = sum_d Wk[j, h*64+d] * q[b, h*64+d]
__global__ void k_t(const float* __restrict__ Wk) {
    int h = blockIdx.x, j0 = blockIdx.y * 128;
    int tid = threadIdx.x;
    int jl = tid & 31, bg = tid >> 5;
    __shared__ float qs[BB][HD];
    __shared__ float wk[32][65];
    for (int l = tid; l < BB * HD; l += 128) {
        int b = l >> 6, d = l & 63;
        qs[b][d] = g_q[b * DM + h * HD + d];
    }
    for (int st = 0; st < 4; ++st) {
        __syncthreads();
#pragma unroll
        for (int i = 0; i < 16; ++i) {
            int l = tid + i * 128;
            int r = l >> 6, d = l & 63;
            wk[r][d] = Wk[(size_t)(j0 + st * 32 + r) * DM + h * HD + d];
        }
        __syncthreads();
        float acc[4] = {0.f, 0.f, 0.f, 0.f};
#pragma unroll 8
        for (int d = 0; d < HD; ++d) {
            float w = wk[jl][d];
#pragma unroll
            for (int bb = 0; bb < 4; ++bb) acc[bb] += w * qs[bg * 4 + bb][d];
        }
        int j = j0 + st * 32 + jl;
#pragma unroll
        for (int bb = 0; bb < 4; ++bb)
            g_t[(size_t)((bg * 4 + bb) * NH + h) * DM + j] = acc[bb];
    }
}

// ---------------- tiled split-K GEMM, double-buffered staging, PROVEN scalar core
// C[M,N] = A[M,K] @ B ; B is [N,K] (kmajor) or [K,N]
template <int MM, int NN, int KK, int SPLITS, bool BKMAJOR>
__global__ void k_gemm(const float* __restrict__ A, const float* __restrict__ Bm,
                       float* __restrict__ part) {
    constexpr int KC = KK / SPLITS, NS = KC / 16;
    int n0 = blockIdx.x * 64, m0 = blockIdx.y * 64, k0 = blockIdx.z * KC;
    __shared__ float Asm[2][16][64];
    __shared__ float Bsm[2][16][64];
    int tid = threadIdx.x;
    int tx = tid & 15, ty = tid >> 4;
    int am = tid >> 2, akq = tid & 3;     // A staging (transposed scatter)
    int bkk = tid >> 4, bn4 = tid & 15;   // B staging (row copy, !BKMAJOR)
    float4 a4, b4;

#define GEMM_LD(kt)                                                                        \
    {                                                                                      \
        a4 = *(const float4*)(A + (size_t)(m0 + am) * KK + k0 + (kt) * 16 + akq * 4);      \
        if (BKMAJOR)                                                                       \
            b4 = *(const float4*)(Bm + (size_t)(n0 + am) * KK + k0 + (kt) * 16 + akq * 4); \
        else                                                                               \
            b4 = *(const float4*)(Bm + (size_t)(k0 + (kt) * 16 + bkk) * NN + n0 + bn4 * 4);\
    }
#define GEMM_ST(bf)                                                                        \
    {                                                                                      \
        Asm[bf][akq * 4 + 0][am] = a4.x; Asm[bf][akq * 4 + 1][am] = a4.y;                  \
        Asm[bf][akq * 4 + 2][am] = a4.z; Asm[bf][akq * 4 + 3][am] = a4.w;                  \
        if (BKMAJOR) {                                                                     \
            Bsm[bf][akq * 4 + 0][am] = b4.x; Bsm[bf][akq * 4 + 1][am] = b4.y;              \
            Bsm[bf][akq * 4 + 2][am] = b4.z; Bsm[bf][akq * 4 + 3][am] = b4.w;              \
        } else {                                                                           \
            *(float4*)&Bsm[bf][bkk][bn4 * 4] = b4;                                         \
        }                                                                                  \
    }

    GEMM_LD(0); GEMM_ST(0);
    float acc[4][4] = {};
    for (int ks = 0; ks < NS; ++ks) {
        __syncthreads();
        int cur = ks & 1;
        if (ks + 1 < NS) GEMM_LD(ks + 1);
#pragma unroll
        for (int kk = 0; kk < 16; ++kk) {
            float4 a = *(const float4*)&Asm[cur][kk][ty * 4];
            float4 b = *(const float4*)&Bsm[cur][kk][tx * 4];
            acc[0][0] += a.x * b.x; acc[0][1] += a.x * b.y; acc[0][2] += a.x * b.z; acc[0][3] += a.x * b.w;
            acc[1][0] += a.y * b.x; acc[1][1] += a.y * b.y; acc[1][2] += a.y * b.z; acc[1][3] += a.y * b.w;
            acc[2][0] += a.z * b.x; acc[2][1] += a.z * b.y; acc[2][2] += a.z * b.z; acc[2][3] += a.z * b.w;
            acc[3][0] += a.w * b.x; acc[3][1] += a.w * b.y; acc[3][2] += a.w * b.z; acc[3][3] += a.w * b.w;
        }
        if (ks + 1 < NS) GEMM_ST((ks + 1) & 1);
    }
#undef GEMM_LD
#undef GEMM_ST
    float* p = part + (size_t)blockIdx.z * MM * NN;
#pragma unroll
    for (int i = 0; i < 4; ++i) {
        float4 v = make_float4(acc[i][0], acc[i][1], acc[i][2], acc[i][3]);
        *(float4*)(p + (size_t)(m0 + ty * 4 + i) * NN + n0 + tx * 4) = v;
    }
}

// ---------------- reduce u partials (8 splits) and write transposed g_uT[b][i][h]
__global__ void k_reduce_ut(const float* __restrict__ part) {
    int e = blockIdx.x * 256 + threadIdx.x;  // 131072 total
    float s = 0.f;
#pragma unroll
    for (int z = 0; z < 8; ++z) s += part[(size_t)z * 131072 + e];
    int m = e >> 9, n = e & 511;
    int b = m >> 4, h = m & 15;
    g_uT[(size_t)(b * DIN + n) * NH + h] = s;
}

// ---------------- FUSED attention: scores (exp, unnormalized) + weighted sum, per (b, s-chunk)
// grid (16 b, 32 chunks of 128 s), block 128
__global__ void k_attn(const float* __restrict__ x2, const float* __restrict__ x3) {
    int b = blockIdx.x, c = blockIdx.y;
    int s0 = c * 128;
    __shared__ __align__(16) float sbuf[DIN * NH];  // 32 KB: phase1 uT[512][16], phase2 at[128][20]
    __shared__ float xs[128][17];                   // 8.7 KB staging, conflict-free reads
    int tid = threadIdx.x;

    // ---- phase 1: scores for this chunk ----
    float (*uT)[NH] = (float(*)[NH])sbuf;
    for (int l = tid; l < DIN * NH; l += 128) sbuf[l] = g_uT[(size_t)b * DIN * NH + l];
    ull acc[8];
#pragma unroll
    for (int p = 0; p < 8; ++p) acc[p] = 0ull;
    const float* x2b = x2 + ((size_t)b * SS + s0) * DIN;
    for (int j0 = 0; j0 < DIN; j0 += 16) {
        __syncthreads();  // first iter also publishes uT
#pragma unroll
        for (int v = 0; v < 4; ++v) {
            int f = tid + v * 128;          // float4 index 0..511
            int rr = f >> 2, jq = f & 3;
            float4 xv = *(const float4*)(x2b + (size_t)rr * DIN + j0 + jq * 4);
            xs[rr][jq * 4 + 0] = xv.x; xs[rr][jq * 4 + 1] = xv.y;
            xs[rr][jq * 4 + 2] = xv.z; xs[rr][jq * 4 + 3] = xv.w;
        }
        __syncthreads();
#pragma unroll
        for (int jj = 0; jj < 16; ++jj) {
            float xv = xs[tid][jj];
            ull xd = pk2(xv, xv);
            const ulonglong2* up = (const ulonglong2*)&uT[j0 + jj][0];
            ulonglong2 u01 = up[0], u23 = up[1], u45 = up[2], u67 = up[3];
            acc[0] = ff2(xd, u01.x, acc[0]);
            acc[1] = ff2(xd, u01.y, acc[1]);
            acc[2] = ff2(xd, u23.x, acc[2]);
            acc[3] = ff2(xd, u23.y, acc[3]);
            acc[4] = ff2(xd, u45.x, acc[4]);
            acc[5] = ff2(xd, u45.y, acc[5]);
            acc[6] = ff2(xd, u67.x, acc[6]);
            acc[7] = ff2(xd, u67.y, acc[7]);
        }
    }
    float ex[NH];
#pragma unroll
    for (int p = 0; p < 8; ++p) {
        float lo, hi;
        up2(lo, hi, acc[p]);
        ex[2 * p]     = __expf(lo * 0.125f);
        ex[2 * p + 1] = __expf(hi * 0.125f);
    }
    __syncthreads();  // all done reading uT
    float (*at)[20] = (float(*)[20])sbuf;
#pragma unroll
    for (int h = 0; h < NH; ++h) at[tid][h] = ex[h];
    __syncthreads();

    // ---- per-chunk sumexp partial (fixed order, deterministic) ----
    if (tid < NH) {
        float s = 0.f;
#pragma unroll 8
        for (int i = 0; i < 128; ++i) s += at[i][tid];
        g_wsump[(c * BB + b) * NH + tid] = s;
    }

    // ---- phase 2: weighted sum ----
    ull wacc[8][4];
#pragma unroll
    for (int p = 0; p < 8; ++p)
#pragma unroll
        for (int d = 0; d < 4; ++d) wacc[p][d] = 0ull;
    int d0 = tid * 4;
    const float* x3b = x3 + ((size_t)b * SS + s0) * DIN + d0;
#pragma unroll 4
    for (int s = 0; s < 128; ++s) {
        float4 xv = *(const float4*)(x3b + (size_t)s * DIN);
        ull xd[4];
        xd[0] = pk2(xv.x, xv.x); xd[1] = pk2(xv.y, xv.y);
        xd[2] = pk2(xv.z, xv.z); xd[3] = pk2(xv.w, xv.w);
        const ulonglong2* wp = (const ulonglong2*)&at[s][0];
        ulonglong2 wA = wp[0], wB = wp[1], wC = wp[2], wD = wp[3];
        ull w[8] = {wA.x, wA.y, wB.x, wB.y, wC.x, wC.y, wD.x, wD.y};
#pragma unroll
        for (int p = 0; p < 8; ++p) {
#pragma unroll
            for (int d = 0; d < 4; ++d) wacc[p][d] = ff2(xd[d], w[p], wacc[p][d]);
        }
    }
    float* yp = g_ypart + ((size_t)(c * BB + b) * NH) * DIN;
#pragma unroll
    for (int p = 0; p < 8; ++p) {
        float lo[4], hi[4];
#pragma unroll
        for (int d = 0; d < 4; ++d) up2(lo[d], hi[d], wacc[p][d]);
        *(float4*)(yp + (2 * p) * DIN + d0)     = make_float4(lo[0], lo[1], lo[2], lo[3]);
        *(float4*)(yp + (2 * p + 1) * DIN + d0) = make_float4(hi[0], hi[1], hi[2], hi[3]);
    }
}

// ---------------- y = (sum over chunks ypart) / (sum over chunks sumexp)
__global__ void k_reduce_norm() {
    int e = blockIdx.x * 256 + threadIdx.x;  // 131072
    int bh = e >> 9;
    float s = 0.f, w = 0.f;
#pragma unroll
    for (int c = 0; c < 32; ++c) {
        s += g_ypart[(size_t)c * 131072 + e];
        w += g_wsump[c * 256 + bh];
    }
    g_y[e] = s / w;
}

// ---------------- av[b, h*64+d] = sum_j (Σ ye_parts + be2)[j] * Wv[j, h*64+d] + bv
__global__ void k_av(const float* __restrict__ part, const float* __restrict__ be2,
                     const float* __restrict__ Wv, const float* __restrict__ bv) {
    int b = blockIdx.x, h = blockIdx.y;
    int d = threadIdx.x & 63, jq = threadIdx.x >> 6;
    __shared__ float yes[DM];
    __shared__ float red[4][64];
    for (int l = threadIdx.x; l < DM; l += 256) {
        float s = be2[l];
#pragma unroll
        for (int z = 0; z < 8; ++z) s += part[(size_t)z * 262144 + (size_t)(b * NH + h) * DM + l];
        yes[l] = s;
    }
    __syncthreads();
    float acc = 0.f;
    const float* wp = Wv + h * HD + d;
#pragma unroll 8
    for (int j = jq * 256; j < jq * 256 + 256; ++j) acc += yes[j] * wp[(size_t)j * DM];
    red[jq][d] = acc;
    __syncthreads();
    if (jq == 0) {
        float s = red[0][d] + red[1][d] + red[2][d] + red[3][d] + bv[h * HD + d];
        g_av[b * DM + h * HD + d] = s;
    }
}

// ---------------- launch ----------------
extern "C" void kernel_launch(void* const* d_in, const int* in_sizes, int n_in,
                              void* d_out, int out_size) {
    const float* x1  = (const float*)d_in[0];
    const float* x2  = (const float*)d_in[1];
    const float* x3  = (const float*)d_in[2];
    const float* We1 = (const float*)d_in[3];
    const float* be1 = (const float*)d_in[4];
    const float* We2 = (const float*)d_in[5];
    const float* be2 = (const float*)d_in[6];
    const float* Wq  = (const float*)d_in[7];
    const float* bq  = (const float*)d_in[8];
    const float* Wk  = (const float*)d_in[9];
    // d_in[10] = bk: cancels in normalization, exactly dropped
    const float* Wv  = (const float*)d_in[11];
    const float* bv  = (const float*)d_in[12];
    const float* Wo  = (const float*)d_in[13];
    const float* bo  = (const float*)d_in[14];
    float* out = (float*)d_out;

    float *pg_part, *pg_x1e, *pg_q, *pg_t, *pg_y, *pg_av;
    cudaGetSymbolAddress((void**)&pg_part, g_part);
    cudaGetSymbolAddress((void**)&pg_x1e,  g_x1e);
    cudaGetSymbolAddress((void**)&pg_q,    g_q);
    cudaGetSymbolAddress((void**)&pg_t,    g_t);
    cudaGetSymbolAddress((void**)&pg_y,    g_y);
    cudaGetSymbolAddress((void**)&pg_av,   g_av);

    // 1) x1e = x1 @ We1 + be1
    k_dense16<512><<<64, 256>>>(x1, We1, be1, pg_x1e);
    // 2) q = x1e @ Wq + bq
    k_dense16<1024><<<64, 256>>>(pg_x1e, Wq, bq, pg_q);
    // 3) t[b,h,j] = Wk_h @ q_h
    k_t<<<dim3(NH, 8), 128>>>(Wk);
    // 4) u = t @ We2^T -> transposed g_uT  (8-way split-K, double-buffered, 8 slabs/block)
    k_gemm<256, 512, 1024, 8, true><<<dim3(8, 4, 8), 256>>>(pg_t, We2, pg_part);
    k_reduce_ut<<<512, 256>>>(pg_part);
    // 5) FUSED scores + weighted-sum + sumexp
    k_attn<<<dim3(BB, 32), 128>>>(x2, x3);
    // 6) normalize into g_y
    k_reduce_norm<<<512, 256>>>();
    // 7) ye partials = y @ We2  (8-way split-K, double-buffered, 4 slabs/block)
    k_gemm<256, 1024, 512, 8, false><<<dim3(16, 4, 8), 256>>>(pg_y, We2, pg_part);
    // 8) av = per-head (Σ ye_parts + be2) @ Wv_h + bv
    k_av<<<dim3(BB, NH), 256>>>(pg_part, be2, Wv, bv);
    // 9) out = av @ Wo + bo
    k_dense16<1024><<<64, 256>>>(pg_av, Wo, bo, out);
}

// round 9
// speedup vs baseline: 1.4429x; 1.0034x over previous
#include <cuda_runtime.h>
#include <cstddef>

#define BB   16
#define SS   4096
#define DIN  512
#define DM   1024
#define NH   16
#define HD   64

// PDL: wait for predecessor's data, then allow successor to begin launching.
#if defined(__CUDA_ARCH__) && (__CUDA_ARCH__ >= 900)
#define PDL_ENTRY() do { cudaGridDependencySynchronize(); cudaTriggerProgrammaticLaunchCompletion(); } while (0)
#else
#define PDL_ENTRY() do { } while (0)
#endif

// ---------------- scratch (no allocations allowed) ----------------
__device__ float g_x1e[BB * DM];
__device__ float g_q[BB * DM];
__device__ float g_t[BB * NH * DM];             // 1 MB
__device__ float g_uT[BB * DIN * NH];           // 0.5 MB, [b][i][h]
__device__ float g_ypart[32 * BB * NH * DIN];   // 16.8 MB, [c][b][h][d]
__device__ float g_wsump[32 * BB * NH];         // per-chunk sum of exp
__device__ float g_y[BB * NH * DIN];
__device__ float g_av[BB * DM];
__device__ float g_part[4194304];               // 16 MB split-K partials

typedef unsigned long long ull;

// ---------------- f32x2 packed-FMA helpers (attention kernels only) ----------------
__device__ __forceinline__ ull pk2(float lo, float hi) {
    ull r;
    asm("mov.b64 %0, {%1, %2};" : "=l"(r) : "f"(lo), "f"(hi));
    return r;
}
__device__ __forceinline__ ull ff2(ull a, ull b, ull c) {
    ull d;
    asm("fma.rn.f32x2 %0, %1, %2, %3;" : "=l"(d) : "l"(a), "l"(b), "l"(c));
    return d;
}
__device__ __forceinline__ void up2(float& lo, float& hi, ull a) {
    asm("mov.b64 {%0, %1}, %2;" : "=f"(lo), "=f"(hi) : "l"(a));
}

// ---------------- fused 16-row dense: out[16][1024] = X[16][K] @ W[K][1024] + bias
template <int K>
__global__ void k_dense16(const float* __restrict__ X, const float* __restrict__ W,
                          const float* __restrict__ bias, float* __restrict__ out) {
    PDL_ENTRY();
    __shared__ float xs[256][17];
    __shared__ float ps[16][256];
    int tid = threadIdx.x;
    int jl = tid & 15, ks = tid >> 4;
    int j = blockIdx.x * 16 + jl;
    float acc[BB];
#pragma unroll
    for (int b = 0; b < BB; ++b) acc[b] = 0.f;

    for (int k0 = 0; k0 < K; k0 += 256) {
        __syncthreads();
#pragma unroll
        for (int i = 0; i < 16; ++i) {
            int l = tid + i * 256;
            int k = l & 255, b = l >> 8;
            xs[k][b] = X[b * K + k0 + k];
        }
        __syncthreads();
#pragma unroll 8
        for (int kk = ks * 16; kk < ks * 16 + 16; ++kk) {
            float w = W[(size_t)(k0 + kk) * DM + j];
#pragma unroll
            for (int b = 0; b < BB; ++b) acc[b] += w * xs[kk][b];
        }
    }
#pragma unroll
    for (int b = 0; b < BB; ++b) ps[ks][b * 16 + jl] = acc[b];
    __syncthreads();
    {
        int b = tid >> 4, jj = tid & 15;
        float s = 0.f;
#pragma unroll
        for (int z = 0; z < 16; ++z) s += ps[z][tid];
        out[b * DM + blockIdx.x * 16 + jj] = s + bias[blockIdx.x * 16 + jj];
    }
}

// ---------------- t[b,h,j] = sum_d Wk[j, h*64+d] * q[b, h*64+d]
__global__ void k_t(const float* __restrict__ Wk) {
    PDL_ENTRY();
    int h = blockIdx.x, j0 = blockIdx.y * 128;
    int tid = threadIdx.x;
    int jl = tid & 31, bg = tid >> 5;
    __shared__ float qs[BB][HD];
    __shared__ float wk[32][65];
    for (int l = tid; l < BB * HD; l += 128) {
        int b = l >> 6, d = l & 63;
        qs[b][d] = g_q[b * DM + h * HD + d];
    }
    for (int st = 0; st < 4; ++st) {
        __syncthreads();
#pragma unroll
        for (int i = 0; i < 16; ++i) {
            int l = tid + i * 128;
            int r = l >> 6, d = l & 63;
            wk[r][d] = Wk[(size_t)(j0 + st * 32 + r) * DM + h * HD + d];
        }
        __syncthreads();
        float acc[4] = {0.f, 0.f, 0.f, 0.f};
#pragma unroll 8
        for (int d = 0; d < HD; ++d) {
            float w = wk[jl][d];
#pragma unroll
            for (int bb = 0; bb < 4; ++bb) acc[bb] += w * qs[bg * 4 + bb][d];
        }
        int j = j0 + st * 32 + jl;
#pragma unroll
        for (int bb = 0; bb < 4; ++bb)
            g_t[(size_t)((bg * 4 + bb) * NH + h) * DM + j] = acc[bb];
    }
}

// ---------------- tiled split-K GEMM, double-buffered staging, proven scalar core
// C[M,N] = A[M,K] @ B ; B is [N,K] (kmajor) or [K,N]
template <int MM, int NN, int KK, int SPLITS, bool BKMAJOR>
__global__ void k_gemm(const float* __restrict__ A, const float* __restrict__ Bm,
                       float* __restrict__ part) {
    PDL_ENTRY();
    constexpr int KC = KK / SPLITS, NS = KC / 16;
    int n0 = blockIdx.x * 64, m0 = blockIdx.y * 64, k0 = blockIdx.z * KC;
    __shared__ float Asm[2][16][64];
    __shared__ float Bsm[2][16][64];
    int tid = threadIdx.x;
    int tx = tid & 15, ty = tid >> 4;
    int am = tid >> 2, akq = tid & 3;     // A staging (transposed scatter)
    int bkk = tid >> 4, bn4 = tid & 15;   // B staging (row copy, !BKMAJOR)
    float4 a4, b4;

#define GEMM_LD(kt)                                                                        \
    {                                                                                      \
        a4 = *(const float4*)(A + (size_t)(m0 + am) * KK + k0 + (kt) * 16 + akq * 4);      \
        if (BKMAJOR)                                                                       \
            b4 = *(const float4*)(Bm + (size_t)(n0 + am) * KK + k0 + (kt) * 16 + akq * 4); \
        else                                                                               \
            b4 = *(const float4*)(Bm + (size_t)(k0 + (kt) * 16 + bkk) * NN + n0 + bn4 * 4);\
    }
#define GEMM_ST(bf)                                                                        \
    {                                                                                      \
        Asm[bf][akq * 4 + 0][am] = a4.x; Asm[bf][akq * 4 + 1][am] = a4.y;                  \
        Asm[bf][akq * 4 + 2][am] = a4.z; Asm[bf][akq * 4 + 3][am] = a4.w;                  \
        if (BKMAJOR) {                                                                     \
            Bsm[bf][akq * 4 + 0][am] = b4.x; Bsm[bf][akq * 4 + 1][am] = b4.y;              \
            Bsm[bf][akq * 4 + 2][am] = b4.z; Bsm[bf][akq * 4 + 3][am] = b4.w;              \
        } else {                                                                           \
            *(float4*)&Bsm[bf][bkk][bn4 * 4] = b4;                                         \
        }                                                                                  \
    }

    GEMM_LD(0); GEMM_ST(0);
    float acc[4][4] = {};
    for (int ks = 0; ks < NS; ++ks) {
        __syncthreads();
        int cur = ks & 1;
        if (ks + 1 < NS) GEMM_LD(ks + 1);
#pragma unroll
        for (int kk = 0; kk < 16; ++kk) {
            float4 a = *(const float4*)&Asm[cur][kk][ty * 4];
            float4 b = *(const float4*)&Bsm[cur][kk][tx * 4];
            acc[0][0] += a.x * b.x; acc[0][1] += a.x * b.y; acc[0][2] += a.x * b.z; acc[0][3] += a.x * b.w;
            acc[1][0] += a.y * b.x; acc[1][1] += a.y * b.y; acc[1][2] += a.y * b.z; acc[1][3] += a.y * b.w;
            acc[2][0] += a.z * b.x; acc[2][1] += a.z * b.y; acc[2][2] += a.z * b.z; acc[2][3] += a.z * b.w;
            acc[3][0] += a.w * b.x; acc[3][1] += a.w * b.y; acc[3][2] += a.w * b.z; acc[3][3] += a.w * b.w;
        }
        if (ks + 1 < NS) GEMM_ST((ks + 1) & 1);
    }
#undef GEMM_LD
#undef GEMM_ST
    float* p = part + (size_t)blockIdx.z * MM * NN;
#pragma unroll
    for (int i = 0; i < 4; ++i) {
        float4 v = make_float4(acc[i][0], acc[i][1], acc[i][2], acc[i][3]);
        *(float4*)(p + (size_t)(m0 + ty * 4 + i) * NN + n0 + tx * 4) = v;
    }
}

// ---------------- reduce u partials (8 splits) and write transposed g_uT[b][i][h]
__global__ void k_reduce_ut(const float* __restrict__ part) {
    PDL_ENTRY();
    int e = blockIdx.x * 256 + threadIdx.x;  // 131072 total
    float s = 0.f;
#pragma unroll
    for (int z = 0; z < 8; ++z) s += part[(size_t)z * 131072 + e];
    int m = e >> 9, n = e & 511;
    int b = m >> 4, h = m & 15;
    g_uT[(size_t)(b * DIN + n) * NH + h] = s;
}

// ---------------- FUSED attention: scores (exp, unnormalized) + weighted sum, per (b, s-chunk)
// grid (16 b, 32 chunks of 128 s), block 128
__global__ void k_attn(const float* __restrict__ x2, const float* __restrict__ x3) {
    PDL_ENTRY();
    int b = blockIdx.x, c = blockIdx.y;
    int s0 = c * 128;
    __shared__ __align__(16) float sbuf[DIN * NH];  // 32 KB: phase1 uT[512][16], phase2 at[128][20]
    __shared__ float xs[128][17];                   // 8.7 KB staging, conflict-free reads
    int tid = threadIdx.x;

    // ---- phase 1: scores for this chunk ----
    float (*uT)[NH] = (float(*)[NH])sbuf;
    for (int l = tid; l < DIN * NH; l += 128) sbuf[l] = g_uT[(size_t)b * DIN * NH + l];
    ull acc[8];
#pragma unroll
    for (int p = 0; p < 8; ++p) acc[p] = 0ull;
    const float* x2b = x2 + ((size_t)b * SS + s0) * DIN;
    for (int j0 = 0; j0 < DIN; j0 += 16) {
        __syncthreads();  // first iter also publishes uT
#pragma unroll
        for (int v = 0; v < 4; ++v) {
            int f = tid + v * 128;          // float4 index 0..511
            int rr = f >> 2, jq = f & 3;
            float4 xv = *(const float4*)(x2b + (size_t)rr * DIN + j0 + jq * 4);
            xs[rr][jq * 4 + 0] = xv.x; xs[rr][jq * 4 + 1] = xv.y;
            xs[rr][jq * 4 + 2] = xv.z; xs[rr][jq * 4 + 3] = xv.w;
        }
        __syncthreads();
#pragma unroll
        for (int jj = 0; jj < 16; ++jj) {
            float xv = xs[tid][jj];
            ull xd = pk2(xv, xv);
            const ulonglong2* up = (const ulonglong2*)&uT[j0 + jj][0];
            ulonglong2 u01 = up[0], u23 = up[1], u45 = up[2], u67 = up[3];
            acc[0] = ff2(xd, u01.x, acc[0]);
            acc[1] = ff2(xd, u01.y, acc[1]);
            acc[2] = ff2(xd, u23.x, acc[2]);
            acc[3] = ff2(xd, u23.y, acc[3]);
            acc[4] = ff2(xd, u45.x, acc[4]);
            acc[5] = ff2(xd, u45.y, acc[5]);
            acc[6] = ff2(xd, u67.x, acc[6]);
            acc[7] = ff2(xd, u67.y, acc[7]);
        }
    }
    float ex[NH];
#pragma unroll
    for (int p = 0; p < 8; ++p) {
        float lo, hi;
        up2(lo, hi, acc[p]);
        ex[2 * p]     = __expf(lo * 0.125f);
        ex[2 * p + 1] = __expf(hi * 0.125f);
    }
    __syncthreads();  // all done reading uT
    float (*at)[20] = (float(*)[20])sbuf;
#pragma unroll
    for (int h = 0; h < NH; ++h) at[tid][h] = ex[h];
    __syncthreads();

    // ---- per-chunk sumexp partial (fixed order, deterministic) ----
    if (tid < NH) {
        float s = 0.f;
#pragma unroll 8
        for (int i = 0; i < 128; ++i) s += at[i][tid];
        g_wsump[(c * BB + b) * NH + tid] = s;
    }

    // ---- phase 2: weighted sum ----
    ull wacc[8][4];
#pragma unroll
    for (int p = 0; p < 8; ++p)
#pragma unroll
        for (int d = 0; d < 4; ++d) wacc[p][d] = 0ull;
    int d0 = tid * 4;
    const float* x3b = x3 + ((size_t)b * SS + s0) * DIN + d0;
#pragma unroll 4
    for (int s = 0; s < 128; ++s) {
        float4 xv = *(const float4*)(x3b + (size_t)s * DIN);
        ull xd[4];
        xd[0] = pk2(xv.x, xv.x); xd[1] = pk2(xv.y, xv.y);
        xd[2] = pk2(xv.z, xv.z); xd[3] = pk2(xv.w, xv.w);
        const ulonglong2* wp = (const ulonglong2*)&at[s][0];
        ulonglong2 wA = wp[0], wB = wp[1], wC = wp[2], wD = wp[3];
        ull w[8] = {wA.x, wA.y, wB.x, wB.y, wC.x, wC.y, wD.x, wD.y};
#pragma unroll
        for (int p = 0; p < 8; ++p) {
#pragma unroll
            for (int d = 0; d < 4; ++d) wacc[p][d] = ff2(xd[d], w[p], wacc[p][d]);
        }
    }
    float* yp = g_ypart + ((size_t)(c * BB + b) * NH) * DIN;
#pragma unroll
    for (int p = 0; p < 8; ++p) {
        float lo[4], hi[4];
#pragma unroll
        for (int d = 0; d < 4; ++d) up2(lo[d], hi[d], wacc[p][d]);
        *(float4*)(yp + (2 * p) * DIN + d0)     = make_float4(lo[0], lo[1], lo[2], lo[3]);
        *(float4*)(yp + (2 * p + 1) * DIN + d0) = make_float4(hi[0], hi[1], hi[2], hi[3]);
    }
}

// ---------------- y = (sum over chunks ypart) / (sum over chunks sumexp)
__global__ void k_reduce_norm() {
    PDL_ENTRY();
    int e = blockIdx.x * 256 + threadIdx.x;  // 131072
    int bh = e >> 9;
    float s = 0.f, w = 0.f;
#pragma unroll
    for (int c = 0; c < 32; ++c) {
        s += g_ypart[(size_t)c * 131072 + e];
        w += g_wsump[c * 256 + bh];
    }
    g_y[e] = s / w;
}

// ---------------- av[b, h*64+d] = sum_j (Σ ye_parts + be2)[j] * Wv[j, h*64+d] + bv
__global__ void k_av(const float* __restrict__ part, const float* __restrict__ be2,
                     const float* __restrict__ Wv, const float* __restrict__ bv) {
    PDL_ENTRY();
    int b = blockIdx.x, h = blockIdx.y;
    int d = threadIdx.x & 63, jq = threadIdx.x >> 6;
    __shared__ float yes[DM];
    __shared__ float red[4][64];
    for (int l = threadIdx.x; l < DM; l += 256) {
        float s = be2[l];
#pragma unroll
        for (int z = 0; z < 8; ++z) s += part[(size_t)z * 262144 + (size_t)(b * NH + h) * DM + l];
        yes[l] = s;
    }
    __syncthreads();
    float acc = 0.f;
    const float* wp = Wv + h * HD + d;
#pragma unroll 8
    for (int j = jq * 256; j < jq * 256 + 256; ++j) acc += yes[j] * wp[(size_t)j * DM];
    red[jq][d] = acc;
    __syncthreads();
    if (jq == 0) {
        float s = red[0][d] + red[1][d] + red[2][d] + red[3][d] + bv[h * HD + d];
        g_av[b * DM + h * HD + d] = s;
    }
}

// ---------------- PDL launcher ----------------
template <typename F, typename... Args>
static inline void pdl_launch(F kern, dim3 g, dim3 b, Args... args) {
    cudaLaunchConfig_t cfg = {};
    cfg.gridDim = g;
    cfg.blockDim = b;
    cfg.dynamicSmemBytes = 0;
    cfg.stream = 0;
    cudaLaunchAttribute at[1];
    at[0].id = cudaLaunchAttributeProgrammaticStreamSerialization;
    at[0].val.programmaticStreamSerializationAllowed = 1;
    cfg.attrs = at;
    cfg.numAttrs = 1;
    cudaLaunchKernelEx(&cfg, kern, args...);
}

// ---------------- launch ----------------
extern "C" void kernel_launch(void* const* d_in, const int* in_sizes, int n_in,
                              void* d_out, int out_size) {
    const float* x1  = (const float*)d_in[0];
    const float* x2  = (const float*)d_in[1];
    const float* x3  = (const float*)d_in[2];
    const float* We1 = (const float*)d_in[3];
    const float* be1 = (const float*)d_in[4];
    const float* We2 = (const float*)d_in[5];
    const float* be2 = (const float*)d_in[6];
    const float* Wq  = (const float*)d_in[7];
    const float* bq  = (const float*)d_in[8];
    const float* Wk  = (const float*)d_in[9];
    // d_in[10] = bk: cancels in normalization, exactly dropped
    const float* Wv  = (const float*)d_in[11];
    const float* bv  = (const float*)d_in[12];
    const float* Wo  = (const float*)d_in[13];
    const float* bo  = (const float*)d_in[14];
    float* out = (float*)d_out;

    float *pg_part, *pg_x1e, *pg_q, *pg_t, *pg_y, *pg_av;
    cudaGetSymbolAddress((void**)&pg_part, g_part);
    cudaGetSymbolAddress((void**)&pg_x1e,  g_x1e);
    cudaGetSymbolAddress((void**)&pg_q,    g_q);
    cudaGetSymbolAddress((void**)&pg_t,    g_t);
    cudaGetSymbolAddress((void**)&pg_y,    g_y);
    cudaGetSymbolAddress((void**)&pg_av,   g_av);

    // 1) x1e = x1 @ We1 + be1
    pdl_launch(k_dense16<512>, dim3(64), dim3(256), x1, We1, be1, pg_x1e);
    // 2) q = x1e @ Wq + bq
    pdl_launch(k_dense16<1024>, dim3(64), dim3(256), (const float*)pg_x1e, Wq, bq, pg_q);
    // 3) t[b,h,j] = Wk_h @ q_h
    pdl_launch(k_t, dim3(NH, 8), dim3(128), Wk);
    // 4) u = t @ We2^T -> transposed g_uT  (8-way split-K, double-buffered)
    pdl_launch(k_gemm<256, 512, 1024, 8, true>, dim3(8, 4, 8), dim3(256),
               (const float*)pg_t, We2, pg_part);
    pdl_launch(k_reduce_ut, dim3(512), dim3(256), (const float*)pg_part);
    // 5) FUSED scores + weighted-sum + sumexp
    pdl_launch(k_attn, dim3(BB, 32), dim3(128), x2, x3);
    // 6) normalize into g_y
    pdl_launch(k_reduce_norm, dim3(512), dim3(256));
    // 7) ye partials = y @ We2  (8-way split-K, double-buffered)
    pdl_launch(k_gemm<256, 1024, 512, 8, false>, dim3(16, 4, 8), dim3(256),
               (const float*)pg_y, We2, pg_part);
    // 8) av = per-head (Σ ye_parts + be2) @ Wv_h + bv
    pdl_launch(k_av, dim3(BB, NH), dim3(256), (const float*)pg_part, be2, Wv, bv);
    // 9) out = av @ Wo + bo
    pdl_launch(k_dense16<1024>, dim3(64), dim3(256), (const float*)pg_av, Wo, bo, out);
}